// round 9
// baseline (speedup 1.0000x reference)
#include <cuda_runtime.h>
#include <cuda_bf16.h>

// Soft-PQ via warp-level HMMA (mma.sync m16n8k16 bf16), hi/lo 3-MMA fp32 emulation.
// logit_k = (2*<x,c_k> - |c_k|^2)/T  (x^2 cancels in softmax).
// R9: SPARSE EXP — softmax is peaked; exp only where l > rowmax - 16.6
// (dropped sum mass <= 1.6e-5). Kills the hidden MUFU wall (134M -> ~3M exps).
// cp.async B-fragment copy overlapped with X staging.

#define KCW 256
#define DM  128
#define TILE_M 64

// ---- smem byte offsets ----
#define OFF_BH  0         // 65536: B frag image (hi)
#define OFF_BL  65536     // 65536: B frag image (lo)
#define OFF_XH  131072    // 17408: X stage hi (64 rows x 272B)
#define OFF_XL  148480    // 17408: X stage lo
#define OFF_C2  165888    // 1024:  c2 * invT (256 f)
#define OFF_STM 166912    // 1024:  max partials [wc*64+row]
#define SMEM_TOTAL 167936
#define XSTRIDE 272       // bytes per staged X row (136 bf16)
#define LSTRIDE 264       // floats per logit row (reuses B region after sync)

__device__ __align__(16) uint2 g_bfH[8][8192];   // [m][((nt*8)+kt)*32+lane]
__device__ __align__(16) uint2 g_bfL[8][8192];
__device__ float g_c2[8 * KCW];

__device__ __forceinline__ void mma_bf16(float* d, const unsigned* a, uint2 b) {
    asm volatile(
        "mma.sync.aligned.m16n8k16.row.col.f32.bf16.bf16.f32 "
        "{%0,%1,%2,%3}, {%4,%5,%6,%7}, {%8,%9}, {%0,%1,%2,%3};"
        : "+f"(d[0]), "+f"(d[1]), "+f"(d[2]), "+f"(d[3])
        : "r"(a[0]), "r"(a[1]), "r"(a[2]), "r"(a[3]), "r"(b.x), "r"(b.y));
}

__device__ __forceinline__ unsigned smem_addr(const void* p) {
    unsigned a;
    asm("{ .reg .u64 t; cvta.to.shared.u64 t, %1; cvt.u32.u64 %0, t; }"
        : "=r"(a) : "l"(p));
    return a;
}
#define CP_ASYNC16(dst, src) \
    asm volatile("cp.async.cg.shared.global [%0], [%1], 16;" :: "r"(dst), "l"(src))
#define CP_ASYNC_COMMIT() asm volatile("cp.async.commit_group;" ::: "memory")
#define CP_ASYNC_WAIT0()  asm volatile("cp.async.wait_group 0;" ::: "memory")

// ======================= prep kernel =======================
// Bakes codebook into hi/lo bf16 HMMA B-fragment images + c2.
// Fragment (m16n8k16 col-major B): lane q=lane%4, g=lane/4; n = nt*8+g;
// reg.x = {k=kt*16+q*2, +1}, reg.y = {k=kt*16+q*2+8, +9}.
__global__ void prep_kernel(const float* __restrict__ cb) {
    int m = blockIdx.x, tid = threadIdx.x;
    if (tid < KCW) {
        const float* src = cb + ((size_t)m * KCW + tid) * DM;
        float c2 = 0.0f;
        for (int d4 = 0; d4 < DM; d4 += 4) {
            float4 v = *(const float4*)(src + d4);
            c2 = fmaf(v.x, v.x, c2); c2 = fmaf(v.y, v.y, c2);
            c2 = fmaf(v.z, v.z, c2); c2 = fmaf(v.w, v.w, c2);
        }
        g_c2[m * KCW + tid] = c2;
    }
    for (int e = tid; e < 8192; e += 256) {
        int lane = e & 31, kt = (e >> 5) & 7, nt = e >> 8;
        int q = lane & 3, g = lane >> 2;
        int n = nt * 8 + g;
        int k0 = kt * 16 + q * 2;
        const float* src = cb + ((size_t)m * KCW + n) * DM;
        float f[4] = { src[k0], src[k0 + 1], src[k0 + 8], src[k0 + 9] };
        unsigned h[4], l[4];
#pragma unroll
        for (int u = 0; u < 4; ++u) {
            __nv_bfloat16 hb = __float2bfloat16_rn(f[u]);
            __nv_bfloat16 lb = __float2bfloat16_rn(f[u] - __bfloat162float(hb));
            h[u] = __bfloat16_as_ushort(hb);
            l[u] = __bfloat16_as_ushort(lb);
        }
        g_bfH[m][e] = make_uint2(h[0] | (h[1] << 16), h[2] | (h[3] << 16));
        g_bfL[m][e] = make_uint2(l[0] | (l[1] << 16), l[2] | (l[3] << 16));
    }
}

// ======================= main kernel =======================
__global__ void __launch_bounds__(256, 1)
softpq_hmma_kernel(const float* __restrict__ x,
                   const float* __restrict__ cb,
                   const void* __restrict__ tptr,
                   float* __restrict__ out,
                   int N)
{
    extern __shared__ char smem[];
    const int tid  = threadIdx.x;
    const int wid  = tid >> 5;
    const int lane = tid & 31;
    const int q    = lane & 3;
    const int g    = lane >> 2;
    const int wr   = wid & 1;    // rows wr*32 .. wr*32+31
    const int wc   = wid >> 1;   // cols wc*64 .. wc*64+63
    const int m    = blockIdx.y;
    const int row0 = blockIdx.x * TILE_M;

    // temperature (robust to int32/float32 scalar encodings)
    float temp;
    {
        float tf = *(const float*)tptr;
        if (tf >= 1e-6f && tf <= 1e6f) temp = tf;
        else { int ti = *(const int*)tptr; temp = (ti != 0) ? (float)ti : 1.0f; }
    }
    const float inv_temp = 1.0f / temp;
    const float two_it = 2.0f * inv_temp;

    // --- B fragment images: async copy (overlaps X staging below) ---
    {
        const uint4* sh = (const uint4*)g_bfH[m];
        const uint4* sl = (const uint4*)g_bfL[m];
        unsigned dh = smem_addr(smem + OFF_BH);
        unsigned dl = smem_addr(smem + OFF_BL);
#pragma unroll
        for (int i = 0; i < 16; ++i) {
            int idx = tid + i * 256;
            CP_ASYNC16(dh + idx * 16, sh + idx);
            CP_ASYNC16(dl + idx * 16, sl + idx);
        }
        CP_ASYNC_COMMIT();
    }

    // --- X tile: coalesced load, hi/lo bf16 split, stage (272B row stride) ---
    {
#pragma unroll
        for (int it = 0; it < 8; ++it) {
            int f = tid + it * 256;           // float4 index
            int r = f >> 5, c4 = f & 31;      // whole warp on one row
            int gr = row0 + r;
            float4 v = make_float4(0.f, 0.f, 0.f, 0.f);
            if (gr < N)
                v = *(const float4*)(x + (size_t)gr * 1024 + m * DM + c4 * 4);
            float fv[4] = { v.x, v.y, v.z, v.w };
            unsigned h[4], l[4];
#pragma unroll
            for (int u = 0; u < 4; ++u) {
                __nv_bfloat16 hb = __float2bfloat16_rn(fv[u]);
                __nv_bfloat16 lb = __float2bfloat16_rn(fv[u] - __bfloat162float(hb));
                h[u] = __bfloat16_as_ushort(hb);
                l[u] = __bfloat16_as_ushort(lb);
            }
            *(uint2*)(smem + OFF_XH + r * XSTRIDE + c4 * 8) =
                make_uint2(h[0] | (h[1] << 16), h[2] | (h[3] << 16));
            *(uint2*)(smem + OFF_XL + r * XSTRIDE + c4 * 8) =
                make_uint2(l[0] | (l[1] << 16), l[2] | (l[3] << 16));
        }
    }

    // --- c2 * invT ---
    ((float*)(smem + OFF_C2))[tid] = g_c2[m * KCW + tid] * inv_temp;
    CP_ASYNC_WAIT0();
    __syncthreads();

    // --- 3-pass HMMA GEMM: acc = <x,c> in fp32 ---
    float acc[2][8][4];
#pragma unroll
    for (int mt = 0; mt < 2; ++mt)
#pragma unroll
        for (int j = 0; j < 8; ++j)
#pragma unroll
            for (int u = 0; u < 4; ++u) acc[mt][j][u] = 0.0f;

    const char* const aB[3] = { smem + OFF_XH, smem + OFF_XH, smem + OFF_XL };
    const char* const bB[3] = { smem + OFF_BH, smem + OFF_BL, smem + OFF_BH };

#pragma unroll
    for (int pass = 0; pass < 3; ++pass) {
        const char* Ab = aB[pass] + (wr * 32 + g) * XSTRIDE + q * 4;
        const char* Bb = bB[pass] + wc * 16384 + lane * 8;
#pragma unroll
        for (int kt = 0; kt < 8; ++kt) {
            unsigned a[2][4];
#pragma unroll
            for (int mt = 0; mt < 2; ++mt) {
                const char* ap = Ab + mt * (16 * XSTRIDE) + kt * 32;
                a[mt][0] = *(const unsigned*)(ap);
                a[mt][1] = *(const unsigned*)(ap + 8 * XSTRIDE);
                a[mt][2] = *(const unsigned*)(ap + 16);
                a[mt][3] = *(const unsigned*)(ap + 8 * XSTRIDE + 16);
            }
#pragma unroll
            for (int j = 0; j < 8; ++j) {
                uint2 b = *(const uint2*)(Bb + (j * 8 + kt) * 256);
                mma_bf16(acc[0][j], a[0], b);
                mma_bf16(acc[1][j], a[1], b);
            }
        }
    }

    // --- logits in registers + per-row MAX only (no exp here!) ---
    {
        const float* c2s = (const float*)(smem + OFF_C2);
        float c2v[8][2];
#pragma unroll
        for (int j = 0; j < 8; ++j) {
            int col = wc * 64 + j * 8 + q * 2;
            c2v[j][0] = c2s[col];
            c2v[j][1] = c2s[col + 1];
        }
#pragma unroll
        for (int mt = 0; mt < 2; ++mt)
#pragma unroll
            for (int j = 0; j < 8; ++j) {
                acc[mt][j][0] = fmaf(acc[mt][j][0], two_it, -c2v[j][0]);
                acc[mt][j][1] = fmaf(acc[mt][j][1], two_it, -c2v[j][1]);
                acc[mt][j][2] = fmaf(acc[mt][j][2], two_it, -c2v[j][0]);
                acc[mt][j][3] = fmaf(acc[mt][j][3], two_it, -c2v[j][1]);
            }

        float mx[2][2];
#pragma unroll
        for (int mt = 0; mt < 2; ++mt)
#pragma unroll
            for (int rh = 0; rh < 2; ++rh) {
                float mv = -3.402823466e38f;
#pragma unroll
                for (int j = 0; j < 8; ++j) {
                    mv = fmaxf(mv, acc[mt][j][rh * 2 + 0]);
                    mv = fmaxf(mv, acc[mt][j][rh * 2 + 1]);
                }
                mv = fmaxf(mv, __shfl_xor_sync(0xffffffffu, mv, 1));
                mv = fmaxf(mv, __shfl_xor_sync(0xffffffffu, mv, 2));
                mx[mt][rh] = mv;
            }

        __syncthreads();   // all warps done with B region -> safe to write logits

        float* Ls  = (float*)smem;
        float* stm = (float*)(smem + OFF_STM);
#pragma unroll
        for (int mt = 0; mt < 2; ++mt)
#pragma unroll
            for (int rh = 0; rh < 2; ++rh) {
                int row = wr * 32 + mt * 16 + rh * 8 + g;
#pragma unroll
                for (int j = 0; j < 8; ++j) {
                    int col = wc * 64 + j * 8 + q * 2;
                    *(float2*)(Ls + row * LSTRIDE + col) =
                        make_float2(acc[mt][j][rh * 2 + 0], acc[mt][j][rh * 2 + 1]);
                }
                if (q == 0) stm[wc * 64 + row] = mx[mt][rh];
            }
    }
    __syncthreads();

    // --- sparse softmax + reconstruction (4 threads / row) ---
    {
        const float* Ls  = (const float*)smem;
        const float* stm = (const float*)(smem + OFF_STM);
        const int row = tid >> 2, qi = tid & 3;
        const float* Lrow = Ls + row * LSTRIDE;

        float M = stm[row];
#pragma unroll
        for (int w = 1; w < 4; ++w) M = fmaxf(M, stm[w * 64 + row]);

        // selective sum over this thread's k-quarter: exp only if within 16.6 of max
        // (dropped mass <= 256*e^-16.6 = 1.6e-5 of S)
        const float cut = M - 16.6f;
        float s = 0.0f;
        const float* Lq = Lrow + qi * 64;
        for (int k4 = 0; k4 < 64; k4 += 4) {
            float4 l4 = *(const float4*)(Lq + k4);
            if (l4.x > cut) s += __expf(l4.x - M);
            if (l4.y > cut) s += __expf(l4.y - M);
            if (l4.z > cut) s += __expf(l4.z - M);
            if (l4.w > cut) s += __expf(l4.w - M);
        }
        s += __shfl_xor_sync(0xffffffffu, s, 1);
        s += __shfl_xor_sync(0xffffffffu, s, 2);

        const float invS = 1.0f / s;
        const float lthr = M + __logf(1e-7f * s);   // p < 1e-7 dropped

        float o[32];
#pragma unroll
        for (int u = 0; u < 32; ++u) o[u] = 0.0f;

        const float* Cq = cb + (size_t)m * KCW * DM + qi * 32;
        for (int k4 = 0; k4 < KCW; k4 += 4) {
            float4 l4 = *(const float4*)(Lrow + k4);
            float lv[4] = { l4.x, l4.y, l4.z, l4.w };
#pragma unroll
            for (int u = 0; u < 4; ++u) {
                if (lv[u] > lthr) {
                    float p = __expf(lv[u] - M) * invS;
                    const float4* cp = (const float4*)(Cq + (size_t)(k4 + u) * DM);
#pragma unroll
                    for (int e = 0; e < 8; ++e) {
                        float4 c = cp[e];
                        o[e * 4 + 0] = fmaf(p, c.x, o[e * 4 + 0]);
                        o[e * 4 + 1] = fmaf(p, c.y, o[e * 4 + 1]);
                        o[e * 4 + 2] = fmaf(p, c.z, o[e * 4 + 2]);
                        o[e * 4 + 3] = fmaf(p, c.w, o[e * 4 + 3]);
                    }
                }
            }
        }

        int gr = row0 + row;
        if (gr < N) {
            float4* op = (float4*)(out + (size_t)gr * 1024 + m * DM + qi * 32);
#pragma unroll
            for (int e = 0; e < 8; ++e)
                op[e] = make_float4(o[e * 4], o[e * 4 + 1], o[e * 4 + 2], o[e * 4 + 3]);
        }
    }
}

extern "C" void kernel_launch(void* const* d_in, const int* in_sizes, int n_in,
                              void* d_out, int out_size)
{
    const float* x  = (const float*)d_in[0];
    const float* cb = (const float*)d_in[1];
    const void*  t  = d_in[2];
    float* out = (float*)d_out;

    int N = in_sizes[0] / 1024;   // D = M*D_M = 1024

    prep_kernel<<<8, 256>>>(cb);

    cudaFuncSetAttribute(softpq_hmma_kernel,
                         cudaFuncAttributeMaxDynamicSharedMemorySize, SMEM_TOTAL);
    dim3 grid((N + TILE_M - 1) / TILE_M, 8);
    softpq_hmma_kernel<<<grid, 256, SMEM_TOTAL>>>(x, cb, t, out, N);
}

// round 11
// speedup vs baseline: 1.4452x; 1.4452x over previous
#include <cuda_runtime.h>
#include <cuda_bf16.h>

// Soft-PQ via warp-level HMMA (mma.sync m16n8k16 bf16), hi/lo 3-MMA fp32 emulation.
// logit_k = (2*<x,c_k> - |c_k|^2)/T  (x^2 cancels in softmax).
// R11: R10 occupancy design + FIX of the warp-pair race on the shared B chunk:
// warps 2wc/2wc+1 share a 16KB chunk, so the hi->lo cp.async swap is now guarded
// by named barriers (bar.sync 1+wc, 64) before each half overwrite.
// 100KB smem + launch_bounds(256,2) => 2 CTAs/SM.

#define KCW 256
#define DM  128
#define TILE_M 64

// ---- smem byte offsets ----
#define OFF_B   0         // 65536: B frag chunk buffer (hi, then per-pair lo swap)
#define OFF_XH  65536     // 17408: X stage hi (64 rows x 272B)
#define OFF_XL  82944     // 17408: X stage lo
#define OFF_C2  100352    // 1024:  c2 * invT (256 f)
#define OFF_STM 101376    // 1024:  max partials [wc*64+row]
#define SMEM_TOTAL 102400
#define XSTRIDE 272       // bytes per staged X row (136 bf16)
#define LSTRIDE 264       // floats per logit row (reuses B+XH region after GEMM)

// B fragment image, kt-major within warp-pair chunk:
// index = wc*2048 + kt*256 + j*32 + lane   (uint2 entries)
__device__ __align__(16) uint2 g_bfH[8][8192];
__device__ __align__(16) uint2 g_bfL[8][8192];
__device__ float g_c2[8 * KCW];

__device__ __forceinline__ void mma_bf16(float* d, const unsigned* a, uint2 b) {
    asm volatile(
        "mma.sync.aligned.m16n8k16.row.col.f32.bf16.bf16.f32 "
        "{%0,%1,%2,%3}, {%4,%5,%6,%7}, {%8,%9}, {%0,%1,%2,%3};"
        : "+f"(d[0]), "+f"(d[1]), "+f"(d[2]), "+f"(d[3])
        : "r"(a[0]), "r"(a[1]), "r"(a[2]), "r"(a[3]), "r"(b.x), "r"(b.y));
}

__device__ __forceinline__ unsigned smem_addr(const void* p) {
    unsigned a;
    asm("{ .reg .u64 t; cvta.to.shared.u64 t, %1; cvt.u32.u64 %0, t; }"
        : "=r"(a) : "l"(p));
    return a;
}
#define CP_ASYNC16(dst, src) \
    asm volatile("cp.async.cg.shared.global [%0], [%1], 16;" :: "r"(dst), "l"(src))
#define CP_ASYNC_COMMIT() asm volatile("cp.async.commit_group;" ::: "memory")
#define CP_ASYNC_WAIT0()  asm volatile("cp.async.wait_group 0;" ::: "memory")
#define CP_ASYNC_WAIT1()  asm volatile("cp.async.wait_group 1;" ::: "memory")
#define PAIR_BAR(id) \
    asm volatile("bar.sync %0, 64;" :: "r"(id) : "memory")

// ======================= prep kernel =======================
// Bakes codebook into hi/lo bf16 HMMA B-fragment images (kt-major chunks) + c2.
// m16n8k16 col-major B frag: lane q=lane%4, g=lane/4; n = nt*8+g;
// reg.x = {k=kt*16+q*2, +1}, reg.y = {+8, +9}.   nt = wc*8 + j.
__global__ void prep_kernel(const float* __restrict__ cb) {
    int m = blockIdx.x, by = blockIdx.y, tid = threadIdx.x;
    if (by == 0) {
        const float* src = cb + ((size_t)m * KCW + tid) * DM;
        float c2 = 0.0f;
        for (int d4 = 0; d4 < DM; d4 += 4) {
            float4 v = *(const float4*)(src + d4);
            c2 = fmaf(v.x, v.x, c2); c2 = fmaf(v.y, v.y, c2);
            c2 = fmaf(v.z, v.z, c2); c2 = fmaf(v.w, v.w, c2);
        }
        g_c2[m * KCW + tid] = c2;
    }
#pragma unroll
    for (int i = 0; i < 8; ++i) {
        int e = by * 2048 + i * 256 + tid;
        int lane = e & 31, j = (e >> 5) & 7, kt = (e >> 8) & 7, wc = (e >> 11) & 3;
        int q = lane & 3, g = lane >> 2;
        int n = (wc * 8 + j) * 8 + g;
        int k0 = kt * 16 + q * 2;
        const float* src = cb + ((size_t)m * KCW + n) * DM;
        float f[4] = { src[k0], src[k0 + 1], src[k0 + 8], src[k0 + 9] };
        unsigned h[4], l[4];
#pragma unroll
        for (int u = 0; u < 4; ++u) {
            __nv_bfloat16 hb = __float2bfloat16_rn(f[u]);
            __nv_bfloat16 lb = __float2bfloat16_rn(f[u] - __bfloat162float(hb));
            h[u] = __bfloat16_as_ushort(hb);
            l[u] = __bfloat16_as_ushort(lb);
        }
        g_bfH[m][e] = make_uint2(h[0] | (h[1] << 16), h[2] | (h[3] << 16));
        g_bfL[m][e] = make_uint2(l[0] | (l[1] << 16), l[2] | (l[3] << 16));
    }
}

// ======================= main kernel =======================
__global__ void __launch_bounds__(256, 2)
softpq_hmma_kernel(const float* __restrict__ x,
                   const float* __restrict__ cb,
                   const void* __restrict__ tptr,
                   float* __restrict__ out,
                   int N)
{
    extern __shared__ char smem[];
    const int tid  = threadIdx.x;
    const int wid  = tid >> 5;
    const int lane = tid & 31;
    const int q    = lane & 3;
    const int g    = lane >> 2;
    const int wr   = wid & 1;    // rows wr*32 .. wr*32+31
    const int wc   = wid >> 1;   // cols wc*64 .. wc*64+63
    const int m    = blockIdx.y;
    const int row0 = blockIdx.x * TILE_M;
    const int barid = 1 + wc;    // named barrier for the warp pair sharing chunk wc

    // temperature (robust to int32/float32 scalar encodings)
    float temp;
    {
        float tf = *(const float*)tptr;
        if (tf >= 1e-6f && tf <= 1e6f) temp = tf;
        else { int ti = *(const int*)tptr; temp = (ti != 0) ? (float)ti : 1.0f; }
    }
    const float inv_temp = 1.0f / temp;
    const float two_it = 2.0f * inv_temp;

    const unsigned chunkB = smem_addr(smem) + OFF_B + wc * 16384;  // pair-shared 16KB

    // --- B hi chunk: async copy (group 0), overlaps X staging; both pair warps
    //     copy identical bytes (benign overlap; own wait covers own dependency) ---
    {
        const uint4* srcH = (const uint4*)(g_bfH[m] + wc * 2048);
#pragma unroll
        for (int i = 0; i < 32; ++i) {
            int idx = lane + i * 32;
            CP_ASYNC16(chunkB + idx * 16, srcH + idx);
        }
        CP_ASYNC_COMMIT();
    }

    // --- X tile: coalesced load, hi/lo bf16 split, stage (272B row stride) ---
    {
#pragma unroll
        for (int it = 0; it < 8; ++it) {
            int f = tid + it * 256;           // float4 index
            int r = f >> 5, c4 = f & 31;      // whole warp on one row
            int gr = row0 + r;
            float4 v = make_float4(0.f, 0.f, 0.f, 0.f);
            if (gr < N)
                v = *(const float4*)(x + (size_t)gr * 1024 + m * DM + c4 * 4);
            float fv[4] = { v.x, v.y, v.z, v.w };
            unsigned h[4], l[4];
#pragma unroll
            for (int u = 0; u < 4; ++u) {
                __nv_bfloat16 hb = __float2bfloat16_rn(fv[u]);
                __nv_bfloat16 lb = __float2bfloat16_rn(fv[u] - __bfloat162float(hb));
                h[u] = __bfloat16_as_ushort(hb);
                l[u] = __bfloat16_as_ushort(lb);
            }
            *(uint2*)(smem + OFF_XH + r * XSTRIDE + c4 * 8) =
                make_uint2(h[0] | (h[1] << 16), h[2] | (h[3] << 16));
            *(uint2*)(smem + OFF_XL + r * XSTRIDE + c4 * 8) =
                make_uint2(l[0] | (l[1] << 16), l[2] | (l[3] << 16));
        }
    }

    // --- c2 * invT ---
    ((float*)(smem + OFF_C2))[tid] = g_c2[m * KCW + tid] * inv_temp;
    CP_ASYNC_WAIT0();          // B hi resident (own copy)
    __syncthreads();           // X visible to all warps

    // --- HMMA GEMM ---
    float acc[2][8][4];
#pragma unroll
    for (int mt = 0; mt < 2; ++mt)
#pragma unroll
        for (int j = 0; j < 8; ++j)
#pragma unroll
            for (int u = 0; u < 4; ++u) acc[mt][j][u] = 0.0f;

    const char* AbH = smem + OFF_XH + (wr * 32 + g) * XSTRIDE + q * 4;
    const char* AbL = smem + OFF_XL + (wr * 32 + g) * XSTRIDE + q * 4;
    const uint4* srcL = (const uint4*)(g_bfL[m] + wc * 2048);

    // merged hi passes: (x_hi + x_lo) * b_hi, kt-major B
#pragma unroll
    for (int kt = 0; kt < 8; ++kt) {
        unsigned ah[2][4], al[2][4];
#pragma unroll
        for (int mt = 0; mt < 2; ++mt) {
            const char* hp = AbH + mt * (16 * XSTRIDE) + kt * 32;
            const char* lp = AbL + mt * (16 * XSTRIDE) + kt * 32;
            ah[mt][0] = *(const unsigned*)(hp);
            ah[mt][1] = *(const unsigned*)(hp + 8 * XSTRIDE);
            ah[mt][2] = *(const unsigned*)(hp + 16);
            ah[mt][3] = *(const unsigned*)(hp + 8 * XSTRIDE + 16);
            al[mt][0] = *(const unsigned*)(lp);
            al[mt][1] = *(const unsigned*)(lp + 8 * XSTRIDE);
            al[mt][2] = *(const unsigned*)(lp + 16);
            al[mt][3] = *(const unsigned*)(lp + 8 * XSTRIDE + 16);
        }
#pragma unroll
        for (int j = 0; j < 8; ++j) {
            uint2 b;
            asm volatile("ld.shared.v2.u32 {%0,%1}, [%2];"
                         : "=r"(b.x), "=r"(b.y)
                         : "r"(chunkB + (kt * 8 + j) * 256 + lane * 8));
            mma_bf16(acc[0][j], ah[0], b);
            mma_bf16(acc[1][j], ah[1], b);
            mma_bf16(acc[0][j], al[0], b);
            mma_bf16(acc[1][j], al[1], b);
        }
        if (kt == 3) {
            // BOTH pair warps must be done reading hi kt0-3 before overwrite
            PAIR_BAR(barid);
            // prefetch lo first half into chunk[0..8K) (group 1)
#pragma unroll
            for (int i = 0; i < 16; ++i) {
                int idx = lane + i * 32;
                CP_ASYNC16(chunkB + idx * 16, srcL + idx);
            }
            CP_ASYNC_COMMIT();
        }
    }
    // both pair warps done reading hi kt4-7 -> safe to overwrite chunk[8K..16K)
    PAIR_BAR(barid);
    {
#pragma unroll
        for (int i = 16; i < 32; ++i) {
            int idx = lane + i * 32;
            CP_ASYNC16(chunkB + idx * 16, srcL + idx);
        }
        CP_ASYNC_COMMIT();
    }
    CP_ASYNC_WAIT1();   // group 1 (lo kt0-3) resident

    // lo pass: x_hi * b_lo
#pragma unroll
    for (int half = 0; half < 2; ++half) {
        if (half == 1) CP_ASYNC_WAIT0();   // group 2 resident
#pragma unroll
        for (int kk = 0; kk < 4; ++kk) {
            int kt = half * 4 + kk;
            unsigned ah[2][4];
#pragma unroll
            for (int mt = 0; mt < 2; ++mt) {
                const char* hp = AbH + mt * (16 * XSTRIDE) + kt * 32;
                ah[mt][0] = *(const unsigned*)(hp);
                ah[mt][1] = *(const unsigned*)(hp + 8 * XSTRIDE);
                ah[mt][2] = *(const unsigned*)(hp + 16);
                ah[mt][3] = *(const unsigned*)(hp + 8 * XSTRIDE + 16);
            }
#pragma unroll
            for (int j = 0; j < 8; ++j) {
                uint2 b;
                asm volatile("ld.shared.v2.u32 {%0,%1}, [%2];"
                             : "=r"(b.x), "=r"(b.y)
                             : "r"(chunkB + (kt * 8 + j) * 256 + lane * 8));
                mma_bf16(acc[0][j], ah[0], b);
                mma_bf16(acc[1][j], ah[1], b);
            }
        }
    }

    // --- logits in registers + per-row MAX only ---
    {
        const float* c2s = (const float*)(smem + OFF_C2);
        float c2v[8][2];
#pragma unroll
        for (int j = 0; j < 8; ++j) {
            int col = wc * 64 + j * 8 + q * 2;
            c2v[j][0] = c2s[col];
            c2v[j][1] = c2s[col + 1];
        }
#pragma unroll
        for (int mt = 0; mt < 2; ++mt)
#pragma unroll
            for (int j = 0; j < 8; ++j) {
                acc[mt][j][0] = fmaf(acc[mt][j][0], two_it, -c2v[j][0]);
                acc[mt][j][1] = fmaf(acc[mt][j][1], two_it, -c2v[j][1]);
                acc[mt][j][2] = fmaf(acc[mt][j][2], two_it, -c2v[j][0]);
                acc[mt][j][3] = fmaf(acc[mt][j][3], two_it, -c2v[j][1]);
            }

        float mx[2][2];
#pragma unroll
        for (int mt = 0; mt < 2; ++mt)
#pragma unroll
            for (int rh = 0; rh < 2; ++rh) {
                float mv = -3.402823466e38f;
#pragma unroll
                for (int j = 0; j < 8; ++j) {
                    mv = fmaxf(mv, acc[mt][j][rh * 2 + 0]);
                    mv = fmaxf(mv, acc[mt][j][rh * 2 + 1]);
                }
                mv = fmaxf(mv, __shfl_xor_sync(0xffffffffu, mv, 1));
                mv = fmaxf(mv, __shfl_xor_sync(0xffffffffu, mv, 2));
                mx[mt][rh] = mv;
            }

        __syncthreads();   // all warps done with B/X regions -> safe to write logits

        float* Ls  = (float*)smem;
        float* stm = (float*)(smem + OFF_STM);
#pragma unroll
        for (int mt = 0; mt < 2; ++mt)
#pragma unroll
            for (int rh = 0; rh < 2; ++rh) {
                int row = wr * 32 + mt * 16 + rh * 8 + g;
#pragma unroll
                for (int j = 0; j < 8; ++j) {
                    int col = wc * 64 + j * 8 + q * 2;
                    *(float2*)(Ls + row * LSTRIDE + col) =
                        make_float2(acc[mt][j][rh * 2 + 0], acc[mt][j][rh * 2 + 1]);
                }
                if (q == 0) stm[wc * 64 + row] = mx[mt][rh];
            }
    }
    __syncthreads();

    // --- sparse softmax + reconstruction (4 threads / row) ---
    {
        const float* Ls  = (const float*)smem;
        const float* stm = (const float*)(smem + OFF_STM);
        const int row = tid >> 2, qi = tid & 3;
        const float* Lrow = Ls + row * LSTRIDE;

        float M = stm[row];
#pragma unroll
        for (int w = 1; w < 4; ++w) M = fmaxf(M, stm[w * 64 + row]);

        // selective sum: exp only within 16.6 of max (dropped mass <= 1.6e-5 of S)
        const float cut = M - 16.6f;
        float s = 0.0f;
        const float* Lq = Lrow + qi * 64;
        for (int k4 = 0; k4 < 64; k4 += 4) {
            float4 l4 = *(const float4*)(Lq + k4);
            if (l4.x > cut) s += __expf(l4.x - M);
            if (l4.y > cut) s += __expf(l4.y - M);
            if (l4.z > cut) s += __expf(l4.z - M);
            if (l4.w > cut) s += __expf(l4.w - M);
        }
        s += __shfl_xor_sync(0xffffffffu, s, 1);
        s += __shfl_xor_sync(0xffffffffu, s, 2);

        const float invS = 1.0f / s;
        const float lthr = M + __logf(1e-7f * s);   // p < 1e-7 dropped

        float o[32];
#pragma unroll
        for (int u = 0; u < 32; ++u) o[u] = 0.0f;

        const float* Cq = cb + (size_t)m * KCW * DM + qi * 32;
        for (int k4 = 0; k4 < KCW; k4 += 4) {
            float4 l4 = *(const float4*)(Lrow + k4);
            float lv[4] = { l4.x, l4.y, l4.z, l4.w };
#pragma unroll
            for (int u = 0; u < 4; ++u) {
                if (lv[u] > lthr) {
                    float p = __expf(lv[u] - M) * invS;
                    const float4* cp = (const float4*)(Cq + (size_t)(k4 + u) * DM);
#pragma unroll
                    for (int e = 0; e < 8; ++e) {
                        float4 c = cp[e];
                        o[e * 4 + 0] = fmaf(p, c.x, o[e * 4 + 0]);
                        o[e * 4 + 1] = fmaf(p, c.y, o[e * 4 + 1]);
                        o[e * 4 + 2] = fmaf(p, c.z, o[e * 4 + 2]);
                        o[e * 4 + 3] = fmaf(p, c.w, o[e * 4 + 3]);
                    }
                }
            }
        }

        int gr = row0 + row;
        if (gr < N) {
            float4* op = (float4*)(out + (size_t)gr * 1024 + m * DM + qi * 32);
#pragma unroll
            for (int e = 0; e < 8; ++e)
                op[e] = make_float4(o[e * 4], o[e * 4 + 1], o[e * 4 + 2], o[e * 4 + 3]);
        }
    }
}

extern "C" void kernel_launch(void* const* d_in, const int* in_sizes, int n_in,
                              void* d_out, int out_size)
{
    const float* x  = (const float*)d_in[0];
    const float* cb = (const float*)d_in[1];
    const void*  t  = d_in[2];
    float* out = (float*)d_out;

    int N = in_sizes[0] / 1024;   // D = M*D_M = 1024

    prep_kernel<<<dim3(8, 4), 256>>>(cb);

    cudaFuncSetAttribute(softpq_hmma_kernel,
                         cudaFuncAttributeMaxDynamicSharedMemorySize, SMEM_TOTAL);
    dim3 grid((N + TILE_M - 1) / TILE_M, 8);
    softpq_hmma_kernel<<<grid, 256, SMEM_TOTAL>>>(x, cb, t, out, N);
}

// round 12
// speedup vs baseline: 1.5404x; 1.0658x over previous
#include <cuda_runtime.h>
#include <cuda_bf16.h>

// Soft-PQ via warp-level HMMA (mma.sync m16n8k16 bf16), hi/lo 3-MMA fp32 emulation.
// logit_k = (2*<x,c_k> - |c_k|^2)/T  (x^2 cancels in softmax).
// R12: epilogue rebuilt around per-row SURVIVOR LISTS (atomic append into the
// dead B region) — removes the 64KB logit staging and the 80xLDS.128/thread
// scans. Pair warps now split B cp.async copies (halve L2 traffic), with
// PAIR_BARs guaranteeing the partner half is resident.
// 100KB smem + launch_bounds(256,2) => 2 CTAs/SM.

#define KCW 256
#define DM  128
#define TILE_M 64
#define CAP 64            // survivor list capacity per row (expected ~3)

// ---- smem byte offsets ----
#define OFF_B   0         // 65536: B frag chunks; after GEMM: survivor lists
#define OFF_XH  65536     // 17408: X stage hi (64 rows x 272B)
#define OFF_XL  82944     // 17408: X stage lo
#define OFF_C2  100352    // 1024:  c2 * invT (256 f)
#define OFF_STM 101376    // 1024:  max partials [wc*64+row]
#define OFF_CNT 102400    // 256:   survivor counters (64 u32)
#define SMEM_TOTAL 102656
#define XSTRIDE 272       // bytes per staged X row (136 bf16)

// B fragment image, kt-major within warp-pair chunk:
// index = wc*2048 + kt*256 + j*32 + lane   (uint2 entries)
__device__ __align__(16) uint2 g_bfH[8][8192];
__device__ __align__(16) uint2 g_bfL[8][8192];
__device__ float g_c2[8 * KCW];

__device__ __forceinline__ void mma_bf16(float* d, const unsigned* a, uint2 b) {
    asm volatile(
        "mma.sync.aligned.m16n8k16.row.col.f32.bf16.bf16.f32 "
        "{%0,%1,%2,%3}, {%4,%5,%6,%7}, {%8,%9}, {%0,%1,%2,%3};"
        : "+f"(d[0]), "+f"(d[1]), "+f"(d[2]), "+f"(d[3])
        : "r"(a[0]), "r"(a[1]), "r"(a[2]), "r"(a[3]), "r"(b.x), "r"(b.y));
}

__device__ __forceinline__ unsigned smem_addr(const void* p) {
    unsigned a;
    asm("{ .reg .u64 t; cvta.to.shared.u64 t, %1; cvt.u32.u64 %0, t; }"
        : "=r"(a) : "l"(p));
    return a;
}
#define CP_ASYNC16(dst, src) \
    asm volatile("cp.async.cg.shared.global [%0], [%1], 16;" :: "r"(dst), "l"(src))
#define CP_ASYNC_COMMIT() asm volatile("cp.async.commit_group;" ::: "memory")
#define CP_ASYNC_WAIT0()  asm volatile("cp.async.wait_group 0;" ::: "memory")
#define CP_ASYNC_WAIT1()  asm volatile("cp.async.wait_group 1;" ::: "memory")
#define PAIR_BAR(id) \
    asm volatile("bar.sync %0, 64;" :: "r"(id) : "memory")

// ======================= prep kernel =======================
// Bakes codebook into hi/lo bf16 HMMA B-fragment images (kt-major chunks) + c2.
// m16n8k16 col-major B frag: lane q=lane%4, g=lane/4; n = nt*8+g;
// reg.x = {k=kt*16+q*2, +1}, reg.y = {+8, +9}.   nt = wc*8 + j.
__global__ void prep_kernel(const float* __restrict__ cb) {
    int m = blockIdx.x, by = blockIdx.y, tid = threadIdx.x;
    if (by == 0) {
        const float* src = cb + ((size_t)m * KCW + tid) * DM;
        float c2 = 0.0f;
        for (int d4 = 0; d4 < DM; d4 += 4) {
            float4 v = *(const float4*)(src + d4);
            c2 = fmaf(v.x, v.x, c2); c2 = fmaf(v.y, v.y, c2);
            c2 = fmaf(v.z, v.z, c2); c2 = fmaf(v.w, v.w, c2);
        }
        g_c2[m * KCW + tid] = c2;
    }
#pragma unroll
    for (int i = 0; i < 8; ++i) {
        int e = by * 2048 + i * 256 + tid;
        int lane = e & 31, j = (e >> 5) & 7, kt = (e >> 8) & 7, wc = (e >> 11) & 3;
        int q = lane & 3, g = lane >> 2;
        int n = (wc * 8 + j) * 8 + g;
        int k0 = kt * 16 + q * 2;
        const float* src = cb + ((size_t)m * KCW + n) * DM;
        float f[4] = { src[k0], src[k0 + 1], src[k0 + 8], src[k0 + 9] };
        unsigned h[4], l[4];
#pragma unroll
        for (int u = 0; u < 4; ++u) {
            __nv_bfloat16 hb = __float2bfloat16_rn(f[u]);
            __nv_bfloat16 lb = __float2bfloat16_rn(f[u] - __bfloat162float(hb));
            h[u] = __bfloat16_as_ushort(hb);
            l[u] = __bfloat16_as_ushort(lb);
        }
        g_bfH[m][e] = make_uint2(h[0] | (h[1] << 16), h[2] | (h[3] << 16));
        g_bfL[m][e] = make_uint2(l[0] | (l[1] << 16), l[2] | (l[3] << 16));
    }
}

// ======================= main kernel =======================
__global__ void __launch_bounds__(256, 2)
softpq_hmma_kernel(const float* __restrict__ x,
                   const float* __restrict__ cb,
                   const void* __restrict__ tptr,
                   float* __restrict__ out,
                   int N)
{
    extern __shared__ char smem[];
    const int tid  = threadIdx.x;
    const int wid  = tid >> 5;
    const int lane = tid & 31;
    const int q    = lane & 3;
    const int g    = lane >> 2;
    const int wr   = wid & 1;    // rows wr*32 .. wr*32+31
    const int wc   = wid >> 1;   // cols wc*64 .. wc*64+63
    const int m    = blockIdx.y;
    const int row0 = blockIdx.x * TILE_M;
    const int barid = 1 + wc;    // named barrier for the warp pair sharing chunk wc

    // temperature (robust to int32/float32 scalar encodings)
    float temp;
    {
        float tf = *(const float*)tptr;
        if (tf >= 1e-6f && tf <= 1e6f) temp = tf;
        else { int ti = *(const int*)tptr; temp = (ti != 0) ? (float)ti : 1.0f; }
    }
    const float inv_temp = 1.0f / temp;
    const float two_it = 2.0f * inv_temp;

    const unsigned chunkB = smem_addr(smem) + OFF_B + wc * 16384;  // pair-shared 16KB

    // --- B hi chunk: SPLIT between pair warps (8KB each), async group 0 ---
    {
        const uint4* srcH = (const uint4*)(g_bfH[m] + wc * 2048);
#pragma unroll
        for (int i = 0; i < 16; ++i) {
            int idx = wr * 512 + lane + i * 32;
            CP_ASYNC16(chunkB + idx * 16, srcH + idx);
        }
        CP_ASYNC_COMMIT();
    }

    // survivor counters zeroed early (visible after the pre-GEMM syncthreads)
    if (tid < 64) ((unsigned*)(smem + OFF_CNT))[tid] = 0u;

    // --- X tile: coalesced load, hi/lo bf16 split, stage (272B row stride) ---
    {
#pragma unroll
        for (int it = 0; it < 8; ++it) {
            int f = tid + it * 256;           // float4 index
            int r = f >> 5, c4 = f & 31;      // whole warp on one row
            int gr = row0 + r;
            float4 v = make_float4(0.f, 0.f, 0.f, 0.f);
            if (gr < N)
                v = *(const float4*)(x + (size_t)gr * 1024 + m * DM + c4 * 4);
            float fv[4] = { v.x, v.y, v.z, v.w };
            unsigned h[4], l[4];
#pragma unroll
            for (int u = 0; u < 4; ++u) {
                __nv_bfloat16 hb = __float2bfloat16_rn(fv[u]);
                __nv_bfloat16 lb = __float2bfloat16_rn(fv[u] - __bfloat162float(hb));
                h[u] = __bfloat16_as_ushort(hb);
                l[u] = __bfloat16_as_ushort(lb);
            }
            *(uint2*)(smem + OFF_XH + r * XSTRIDE + c4 * 8) =
                make_uint2(h[0] | (h[1] << 16), h[2] | (h[3] << 16));
            *(uint2*)(smem + OFF_XL + r * XSTRIDE + c4 * 8) =
                make_uint2(l[0] | (l[1] << 16), l[2] | (l[3] << 16));
        }
    }

    // --- c2 * invT ---
    ((float*)(smem + OFF_C2))[tid] = g_c2[m * KCW + tid] * inv_temp;
    CP_ASYNC_WAIT0();          // own half of B hi resident
    __syncthreads();           // X + partner's B half + counters visible

    // --- HMMA GEMM ---
    float acc[2][8][4];
#pragma unroll
    for (int mt = 0; mt < 2; ++mt)
#pragma unroll
        for (int j = 0; j < 8; ++j)
#pragma unroll
            for (int u = 0; u < 4; ++u) acc[mt][j][u] = 0.0f;

    const char* AbH = smem + OFF_XH + (wr * 32 + g) * XSTRIDE + q * 4;
    const char* AbL = smem + OFF_XL + (wr * 32 + g) * XSTRIDE + q * 4;
    const uint4* srcL = (const uint4*)(g_bfL[m] + wc * 2048);

    // merged hi passes: (x_hi + x_lo) * b_hi, kt-major B
#pragma unroll
    for (int kt = 0; kt < 8; ++kt) {
        unsigned ah[2][4], al[2][4];
#pragma unroll
        for (int mt = 0; mt < 2; ++mt) {
            const char* hp = AbH + mt * (16 * XSTRIDE) + kt * 32;
            const char* lp = AbL + mt * (16 * XSTRIDE) + kt * 32;
            ah[mt][0] = *(const unsigned*)(hp);
            ah[mt][1] = *(const unsigned*)(hp + 8 * XSTRIDE);
            ah[mt][2] = *(const unsigned*)(hp + 16);
            ah[mt][3] = *(const unsigned*)(hp + 8 * XSTRIDE + 16);
            al[mt][0] = *(const unsigned*)(lp);
            al[mt][1] = *(const unsigned*)(lp + 8 * XSTRIDE);
            al[mt][2] = *(const unsigned*)(lp + 16);
            al[mt][3] = *(const unsigned*)(lp + 8 * XSTRIDE + 16);
        }
#pragma unroll
        for (int j = 0; j < 8; ++j) {
            uint2 b;
            asm volatile("ld.shared.v2.u32 {%0,%1}, [%2];"
                         : "=r"(b.x), "=r"(b.y)
                         : "r"(chunkB + (kt * 8 + j) * 256 + lane * 8));
            mma_bf16(acc[0][j], ah[0], b);
            mma_bf16(acc[1][j], ah[1], b);
            mma_bf16(acc[0][j], al[0], b);
            mma_bf16(acc[1][j], al[1], b);
        }
        if (kt == 3) {
            // both pair warps done reading hi kt0-3 -> overwrite chunk[0..8K)
            PAIR_BAR(barid);
            // lo first half, SPLIT between pair warps (group 1)
#pragma unroll
            for (int i = 0; i < 8; ++i) {
                int idx = wr * 256 + lane + i * 32;
                CP_ASYNC16(chunkB + idx * 16, srcL + idx);
            }
            CP_ASYNC_COMMIT();
        }
    }
    // both pair warps done reading hi kt4-7 -> overwrite chunk[8K..16K)
    PAIR_BAR(barid);
    {
        // lo second half, SPLIT between pair warps (group 2)
#pragma unroll
        for (int i = 0; i < 8; ++i) {
            int idx = 512 + wr * 256 + lane + i * 32;
            CP_ASYNC16(chunkB + idx * 16, srcL + idx);
        }
        CP_ASYNC_COMMIT();
    }
    CP_ASYNC_WAIT1();   // own group 1 done
    PAIR_BAR(barid);    // partner's group 1 also done -> lo kt0-3 fully resident

    // lo pass: x_hi * b_lo
#pragma unroll
    for (int half = 0; half < 2; ++half) {
        if (half == 1) {
            CP_ASYNC_WAIT0();    // own group 2 done
            PAIR_BAR(barid);     // partner's too -> lo kt4-7 resident
        }
#pragma unroll
        for (int kk = 0; kk < 4; ++kk) {
            int kt = half * 4 + kk;
            unsigned ah[2][4];
#pragma unroll
            for (int mt = 0; mt < 2; ++mt) {
                const char* hp = AbH + mt * (16 * XSTRIDE) + kt * 32;
                ah[mt][0] = *(const unsigned*)(hp);
                ah[mt][1] = *(const unsigned*)(hp + 8 * XSTRIDE);
                ah[mt][2] = *(const unsigned*)(hp + 16);
                ah[mt][3] = *(const unsigned*)(hp + 8 * XSTRIDE + 16);
            }
#pragma unroll
            for (int j = 0; j < 8; ++j) {
                uint2 b;
                asm volatile("ld.shared.v2.u32 {%0,%1}, [%2];"
                             : "=r"(b.x), "=r"(b.y)
                             : "r"(chunkB + (kt * 8 + j) * 256 + lane * 8));
                mma_bf16(acc[0][j], ah[0], b);
                mma_bf16(acc[1][j], ah[1], b);
            }
        }
    }

    // --- logits in registers + per-row quarter-MAX to smem ---
    {
        const float* c2s = (const float*)(smem + OFF_C2);
        float c2v[8][2];
#pragma unroll
        for (int j = 0; j < 8; ++j) {
            int col = wc * 64 + j * 8 + q * 2;
            c2v[j][0] = c2s[col];
            c2v[j][1] = c2s[col + 1];
        }
#pragma unroll
        for (int mt = 0; mt < 2; ++mt)
#pragma unroll
            for (int j = 0; j < 8; ++j) {
                acc[mt][j][0] = fmaf(acc[mt][j][0], two_it, -c2v[j][0]);
                acc[mt][j][1] = fmaf(acc[mt][j][1], two_it, -c2v[j][1]);
                acc[mt][j][2] = fmaf(acc[mt][j][2], two_it, -c2v[j][0]);
                acc[mt][j][3] = fmaf(acc[mt][j][3], two_it, -c2v[j][1]);
            }

        float* stm = (float*)(smem + OFF_STM);
#pragma unroll
        for (int mt = 0; mt < 2; ++mt)
#pragma unroll
            for (int rh = 0; rh < 2; ++rh) {
                float mv = -3.402823466e38f;
#pragma unroll
                for (int j = 0; j < 8; ++j) {
                    mv = fmaxf(mv, acc[mt][j][rh * 2 + 0]);
                    mv = fmaxf(mv, acc[mt][j][rh * 2 + 1]);
                }
                mv = fmaxf(mv, __shfl_xor_sync(0xffffffffu, mv, 1));
                mv = fmaxf(mv, __shfl_xor_sync(0xffffffffu, mv, 2));
                if (q == 0) stm[wc * 64 + (wr * 32 + mt * 16 + rh * 8 + g)] = mv;
            }
    }
    __syncthreads();   // stm complete; B reads done -> B region reusable as lists

    // --- survivor append: exp only within 16.6 of global row max ---
    // (dropped mass <= 1.6e-5 of S)
    {
        const float* stm = (const float*)(smem + OFF_STM);
        unsigned* cnt = (unsigned*)(smem + OFF_CNT);
        uint2* list = (uint2*)(smem + OFF_B);
#pragma unroll
        for (int mt = 0; mt < 2; ++mt)
#pragma unroll
            for (int rh = 0; rh < 2; ++rh) {
                int row = wr * 32 + mt * 16 + rh * 8 + g;
                float M = fmaxf(fmaxf(stm[row], stm[64 + row]),
                                fmaxf(stm[128 + row], stm[192 + row]));
                float cut = M - 16.6f;
#pragma unroll
                for (int j = 0; j < 8; ++j) {
#pragma unroll
                    for (int u = 0; u < 2; ++u) {
                        float l = acc[mt][j][rh * 2 + u];
                        if (l > cut) {
                            unsigned idx = atomicAdd(&cnt[row], 1u);
                            if (idx < CAP) {
                                unsigned k = (unsigned)(wc * 64 + j * 8 + q * 2 + u);
                                list[row * CAP + idx] =
                                    make_uint2(k, __float_as_uint(__expf(l - M)));
                            }
                        }
                    }
                }
            }
    }
    __syncthreads();

    // --- reconstruction from survivor lists (4 threads / row) ---
    {
        const unsigned* cnt = (const unsigned*)(smem + OFF_CNT);
        const uint2* list = (const uint2*)(smem + OFF_B);
        const int row = tid >> 2, qi = tid & 3;

        int n = (int)cnt[row];
        if (n > CAP) n = CAP;

        float S = 0.0f;
        for (int i = 0; i < n; ++i)
            S += __uint_as_float(list[row * CAP + i].y);
        const float invS = 1.0f / S;

        float o[32];
#pragma unroll
        for (int u = 0; u < 32; ++u) o[u] = 0.0f;

        const float* Cq = cb + (size_t)m * KCW * DM + qi * 32;
        for (int i = 0; i < n; ++i) {
            uint2 ent = list[row * CAP + i];
            float p = __uint_as_float(ent.y) * invS;
            const float4* cp = (const float4*)(Cq + (size_t)ent.x * DM);
#pragma unroll
            for (int e = 0; e < 8; ++e) {
                float4 c = cp[e];
                o[e * 4 + 0] = fmaf(p, c.x, o[e * 4 + 0]);
                o[e * 4 + 1] = fmaf(p, c.y, o[e * 4 + 1]);
                o[e * 4 + 2] = fmaf(p, c.z, o[e * 4 + 2]);
                o[e * 4 + 3] = fmaf(p, c.w, o[e * 4 + 3]);
            }
        }

        int gr = row0 + row;
        if (gr < N) {
            float4* op = (float4*)(out + (size_t)gr * 1024 + m * DM + qi * 32);
#pragma unroll
            for (int e = 0; e < 8; ++e)
                op[e] = make_float4(o[e * 4], o[e * 4 + 1], o[e * 4 + 2], o[e * 4 + 3]);
        }
    }
}

extern "C" void kernel_launch(void* const* d_in, const int* in_sizes, int n_in,
                              void* d_out, int out_size)
{
    const float* x  = (const float*)d_in[0];
    const float* cb = (const float*)d_in[1];
    const void*  t  = d_in[2];
    float* out = (float*)d_out;

    int N = in_sizes[0] / 1024;   // D = M*D_M = 1024

    prep_kernel<<<dim3(8, 4), 256>>>(cb);

    cudaFuncSetAttribute(softpq_hmma_kernel,
                         cudaFuncAttributeMaxDynamicSharedMemorySize, SMEM_TOTAL);
    dim3 grid((N + TILE_M - 1) / TILE_M, 8);
    softpq_hmma_kernel<<<grid, 256, SMEM_TOTAL>>>(x, cb, t, out, N);
}

// round 13
// speedup vs baseline: 1.6133x; 1.0473x over previous
#include <cuda_runtime.h>
#include <cuda_bf16.h>

// Soft-PQ via warp-level HMMA (mma.sync m16n8k16 bf16), hi/lo 3-MMA fp32 emulation.
// logit_k = (2*<x,c_k> - |c_k|^2)/T  (x^2 cancels in softmax).
// R13: B FRAGMENTS STRAIGHT FROM GLOBAL (LDG.64 into regs, L1-resident image) —
// deletes the 128KB cp.async staging, the smem B buffer, and all mid-GEMM
// pair-barriers. Single fused kt-loop does all 3 emulation passes (6 MMA/j).
// Smem 100KB -> 37KB; survivor-list epilogue (R12) kept.

#define KCW 256
#define DM  128
#define TILE_M 64
#define CAP 64            // survivor list capacity per row (expected ~3)

// ---- smem byte offsets ----
#define OFF_XH  0         // 17408: X stage hi (64 rows x 272B); lists after GEMM
#define OFF_XL  17408     // 17408: X stage lo
#define OFF_C2  34816     // 1024:  c2 * invT (256 f)
#define OFF_STM 35840     // 1024:  max partials [wc*64+row]
#define OFF_CNT 36864     // 256:   survivor counters (64 u32)
#define SMEM_TOTAL 37120
#define XSTRIDE 272       // bytes per staged X row (136 bf16)

// B fragment image, kt-major within warp-pair chunk:
// index = wc*2048 + kt*256 + j*32 + lane   (uint2 entries)
__device__ __align__(16) uint2 g_bfH[8][8192];
__device__ __align__(16) uint2 g_bfL[8][8192];
__device__ float g_c2[8 * KCW];

__device__ __forceinline__ void mma_bf16(float* d, const unsigned* a, uint2 b) {
    asm volatile(
        "mma.sync.aligned.m16n8k16.row.col.f32.bf16.bf16.f32 "
        "{%0,%1,%2,%3}, {%4,%5,%6,%7}, {%8,%9}, {%0,%1,%2,%3};"
        : "+f"(d[0]), "+f"(d[1]), "+f"(d[2]), "+f"(d[3])
        : "r"(a[0]), "r"(a[1]), "r"(a[2]), "r"(a[3]), "r"(b.x), "r"(b.y));
}

// ======================= prep kernel =======================
// Bakes codebook into hi/lo bf16 HMMA B-fragment images (kt-major chunks) + c2.
// m16n8k16 col-major B frag: lane q=lane%4, g=lane/4; n = nt*8+g;
// reg.x = {k=kt*16+q*2, +1}, reg.y = {+8, +9}.   nt = wc*8 + j.
__global__ void prep_kernel(const float* __restrict__ cb) {
    int m = blockIdx.x, by = blockIdx.y, tid = threadIdx.x;
    if (by == 0) {
        const float* src = cb + ((size_t)m * KCW + tid) * DM;
        float c2 = 0.0f;
        for (int d4 = 0; d4 < DM; d4 += 4) {
            float4 v = *(const float4*)(src + d4);
            c2 = fmaf(v.x, v.x, c2); c2 = fmaf(v.y, v.y, c2);
            c2 = fmaf(v.z, v.z, c2); c2 = fmaf(v.w, v.w, c2);
        }
        g_c2[m * KCW + tid] = c2;
    }
#pragma unroll
    for (int i = 0; i < 8; ++i) {
        int e = by * 2048 + i * 256 + tid;
        int lane = e & 31, j = (e >> 5) & 7, kt = (e >> 8) & 7, wc = (e >> 11) & 3;
        int q = lane & 3, g = lane >> 2;
        int n = (wc * 8 + j) * 8 + g;
        int k0 = kt * 16 + q * 2;
        const float* src = cb + ((size_t)m * KCW + n) * DM;
        float f[4] = { src[k0], src[k0 + 1], src[k0 + 8], src[k0 + 9] };
        unsigned h[4], l[4];
#pragma unroll
        for (int u = 0; u < 4; ++u) {
            __nv_bfloat16 hb = __float2bfloat16_rn(f[u]);
            __nv_bfloat16 lb = __float2bfloat16_rn(f[u] - __bfloat162float(hb));
            h[u] = __bfloat16_as_ushort(hb);
            l[u] = __bfloat16_as_ushort(lb);
        }
        g_bfH[m][e] = make_uint2(h[0] | (h[1] << 16), h[2] | (h[3] << 16));
        g_bfL[m][e] = make_uint2(l[0] | (l[1] << 16), l[2] | (l[3] << 16));
    }
}

// ======================= main kernel =======================
__global__ void __launch_bounds__(256, 2)
softpq_hmma_kernel(const float* __restrict__ x,
                   const float* __restrict__ cb,
                   const void* __restrict__ tptr,
                   float* __restrict__ out,
                   int N)
{
    extern __shared__ char smem[];
    const int tid  = threadIdx.x;
    const int wid  = tid >> 5;
    const int lane = tid & 31;
    const int q    = lane & 3;
    const int g    = lane >> 2;
    const int wr   = wid & 1;    // rows wr*32 .. wr*32+31
    const int wc   = wid >> 1;   // cols wc*64 .. wc*64+63
    const int m    = blockIdx.y;
    const int row0 = blockIdx.x * TILE_M;

    // temperature (robust to int32/float32 scalar encodings)
    float temp;
    {
        float tf = *(const float*)tptr;
        if (tf >= 1e-6f && tf <= 1e6f) temp = tf;
        else { int ti = *(const int*)tptr; temp = (ti != 0) ? (float)ti : 1.0f; }
    }
    const float inv_temp = 1.0f / temp;
    const float two_it = 2.0f * inv_temp;

    // survivor counters zeroed early (visible after the pre-GEMM syncthreads)
    if (tid < 64) ((unsigned*)(smem + OFF_CNT))[tid] = 0u;

    // --- X tile: coalesced load, hi/lo bf16 split, stage (272B row stride) ---
    {
#pragma unroll
        for (int it = 0; it < 8; ++it) {
            int f = tid + it * 256;           // float4 index
            int r = f >> 5, c4 = f & 31;      // whole warp on one row
            int gr = row0 + r;
            float4 v = make_float4(0.f, 0.f, 0.f, 0.f);
            if (gr < N)
                v = *(const float4*)(x + (size_t)gr * 1024 + m * DM + c4 * 4);
            float fv[4] = { v.x, v.y, v.z, v.w };
            unsigned h[4], l[4];
#pragma unroll
            for (int u = 0; u < 4; ++u) {
                __nv_bfloat16 hb = __float2bfloat16_rn(fv[u]);
                __nv_bfloat16 lb = __float2bfloat16_rn(fv[u] - __bfloat162float(hb));
                h[u] = __bfloat16_as_ushort(hb);
                l[u] = __bfloat16_as_ushort(lb);
            }
            *(uint2*)(smem + OFF_XH + r * XSTRIDE + c4 * 8) =
                make_uint2(h[0] | (h[1] << 16), h[2] | (h[3] << 16));
            *(uint2*)(smem + OFF_XL + r * XSTRIDE + c4 * 8) =
                make_uint2(l[0] | (l[1] << 16), l[2] | (l[3] << 16));
        }
    }

    // --- c2 * invT ---
    ((float*)(smem + OFF_C2))[tid] = g_c2[m * KCW + tid] * inv_temp;
    __syncthreads();           // X stage + counters visible

    // --- fused HMMA GEMM: B frags straight from global (L1-resident image) ---
    float acc[2][8][4];
#pragma unroll
    for (int mt = 0; mt < 2; ++mt)
#pragma unroll
        for (int j = 0; j < 8; ++j)
#pragma unroll
            for (int u = 0; u < 4; ++u) acc[mt][j][u] = 0.0f;

    const char* AbH = smem + OFF_XH + (wr * 32 + g) * XSTRIDE + q * 4;
    const char* AbL = smem + OFF_XL + (wr * 32 + g) * XSTRIDE + q * 4;
    const uint2* pH = g_bfH[m] + wc * 2048 + lane;
    const uint2* pL = g_bfL[m] + wc * 2048 + lane;

#pragma unroll 1
    for (int kt = 0; kt < 8; ++kt) {
        // B frags for this kt: 16 independent LDG.64 (deep MLP)
        uint2 bh[8], bl[8];
#pragma unroll
        for (int j = 0; j < 8; ++j) bh[j] = __ldg(pH + kt * 256 + j * 32);
#pragma unroll
        for (int j = 0; j < 8; ++j) bl[j] = __ldg(pL + kt * 256 + j * 32);

        // A frags (hi + lo) from smem
        unsigned ah[2][4], al[2][4];
#pragma unroll
        for (int mt = 0; mt < 2; ++mt) {
            const char* hp = AbH + mt * (16 * XSTRIDE) + kt * 32;
            const char* lp = AbL + mt * (16 * XSTRIDE) + kt * 32;
            ah[mt][0] = *(const unsigned*)(hp);
            ah[mt][1] = *(const unsigned*)(hp + 8 * XSTRIDE);
            ah[mt][2] = *(const unsigned*)(hp + 16);
            ah[mt][3] = *(const unsigned*)(hp + 8 * XSTRIDE + 16);
            al[mt][0] = *(const unsigned*)(lp);
            al[mt][1] = *(const unsigned*)(lp + 8 * XSTRIDE);
            al[mt][2] = *(const unsigned*)(lp + 16);
            al[mt][3] = *(const unsigned*)(lp + 8 * XSTRIDE + 16);
        }

        // all 3 emulation passes fused: xh*bh, xl*bh, xh*bl
#pragma unroll
        for (int j = 0; j < 8; ++j) {
            mma_bf16(acc[0][j], ah[0], bh[j]);
            mma_bf16(acc[1][j], ah[1], bh[j]);
            mma_bf16(acc[0][j], al[0], bh[j]);
            mma_bf16(acc[1][j], al[1], bh[j]);
            mma_bf16(acc[0][j], ah[0], bl[j]);
            mma_bf16(acc[1][j], ah[1], bl[j]);
        }
    }

    // --- logits in registers + per-row quarter-MAX to smem ---
    {
        const float* c2s = (const float*)(smem + OFF_C2);
        float c2v[8][2];
#pragma unroll
        for (int j = 0; j < 8; ++j) {
            int col = wc * 64 + j * 8 + q * 2;
            c2v[j][0] = c2s[col];
            c2v[j][1] = c2s[col + 1];
        }
#pragma unroll
        for (int mt = 0; mt < 2; ++mt)
#pragma unroll
            for (int j = 0; j < 8; ++j) {
                acc[mt][j][0] = fmaf(acc[mt][j][0], two_it, -c2v[j][0]);
                acc[mt][j][1] = fmaf(acc[mt][j][1], two_it, -c2v[j][1]);
                acc[mt][j][2] = fmaf(acc[mt][j][2], two_it, -c2v[j][0]);
                acc[mt][j][3] = fmaf(acc[mt][j][3], two_it, -c2v[j][1]);
            }

        float* stm = (float*)(smem + OFF_STM);
#pragma unroll
        for (int mt = 0; mt < 2; ++mt)
#pragma unroll
            for (int rh = 0; rh < 2; ++rh) {
                float mv = -3.402823466e38f;
#pragma unroll
                for (int j = 0; j < 8; ++j) {
                    mv = fmaxf(mv, acc[mt][j][rh * 2 + 0]);
                    mv = fmaxf(mv, acc[mt][j][rh * 2 + 1]);
                }
                mv = fmaxf(mv, __shfl_xor_sync(0xffffffffu, mv, 1));
                mv = fmaxf(mv, __shfl_xor_sync(0xffffffffu, mv, 2));
                if (q == 0) stm[wc * 64 + (wr * 32 + mt * 16 + rh * 8 + g)] = mv;
            }
    }
    __syncthreads();   // stm complete; X-stage reads done -> region reusable as lists

    // --- survivor append: exp only within 16.6 of global row max ---
    // (dropped mass <= 1.6e-5 of S)
    {
        const float* stm = (const float*)(smem + OFF_STM);
        unsigned* cnt = (unsigned*)(smem + OFF_CNT);
        uint2* list = (uint2*)(smem + OFF_XH);
#pragma unroll
        for (int mt = 0; mt < 2; ++mt)
#pragma unroll
            for (int rh = 0; rh < 2; ++rh) {
                int row = wr * 32 + mt * 16 + rh * 8 + g;
                float M = fmaxf(fmaxf(stm[row], stm[64 + row]),
                                fmaxf(stm[128 + row], stm[192 + row]));
                float cut = M - 16.6f;
#pragma unroll
                for (int j = 0; j < 8; ++j) {
#pragma unroll
                    for (int u = 0; u < 2; ++u) {
                        float l = acc[mt][j][rh * 2 + u];
                        if (l > cut) {
                            unsigned idx = atomicAdd(&cnt[row], 1u);
                            if (idx < CAP) {
                                unsigned k = (unsigned)(wc * 64 + j * 8 + q * 2 + u);
                                list[row * CAP + idx] =
                                    make_uint2(k, __float_as_uint(__expf(l - M)));
                            }
                        }
                    }
                }
            }
    }
    __syncthreads();

    // --- reconstruction from survivor lists (4 threads / row) ---
    {
        const unsigned* cnt = (const unsigned*)(smem + OFF_CNT);
        const uint2* list = (const uint2*)(smem + OFF_XH);
        const int row = tid >> 2, qi = tid & 3;

        int n = (int)cnt[row];
        if (n > CAP) n = CAP;

        float S = 0.0f;
        for (int i = 0; i < n; ++i)
            S += __uint_as_float(list[row * CAP + i].y);
        const float invS = 1.0f / S;

        float o[32];
#pragma unroll
        for (int u = 0; u < 32; ++u) o[u] = 0.0f;

        const float* Cq = cb + (size_t)m * KCW * DM + qi * 32;
        for (int i = 0; i < n; ++i) {
            uint2 ent = list[row * CAP + i];
            float p = __uint_as_float(ent.y) * invS;
            const float4* cp = (const float4*)(Cq + (size_t)ent.x * DM);
#pragma unroll
            for (int e = 0; e < 8; ++e) {
                float4 c = cp[e];
                o[e * 4 + 0] = fmaf(p, c.x, o[e * 4 + 0]);
                o[e * 4 + 1] = fmaf(p, c.y, o[e * 4 + 1]);
                o[e * 4 + 2] = fmaf(p, c.z, o[e * 4 + 2]);
                o[e * 4 + 3] = fmaf(p, c.w, o[e * 4 + 3]);
            }
        }

        int gr = row0 + row;
        if (gr < N) {
            float4* op = (float4*)(out + (size_t)gr * 1024 + m * DM + qi * 32);
#pragma unroll
            for (int e = 0; e < 8; ++e)
                op[e] = make_float4(o[e * 4], o[e * 4 + 1], o[e * 4 + 2], o[e * 4 + 3]);
        }
    }
}

extern "C" void kernel_launch(void* const* d_in, const int* in_sizes, int n_in,
                              void* d_out, int out_size)
{
    const float* x  = (const float*)d_in[0];
    const float* cb = (const float*)d_in[1];
    const void*  t  = d_in[2];
    float* out = (float*)d_out;

    int N = in_sizes[0] / 1024;   // D = M*D_M = 1024

    prep_kernel<<<dim3(8, 4), 256>>>(cb);

    cudaFuncSetAttribute(softpq_hmma_kernel,
                         cudaFuncAttributeMaxDynamicSharedMemorySize, SMEM_TOTAL);
    dim3 grid((N + TILE_M - 1) / TILE_M, 8);
    softpq_hmma_kernel<<<grid, 256, SMEM_TOTAL>>>(x, cb, t, out, N);
}

// round 14
// speedup vs baseline: 2.3393x; 1.4500x over previous
#include <cuda_runtime.h>
#include <cuda_bf16.h>

// Soft-PQ via warp-level HMMA (mma.sync m16n8k16 bf16), hi/lo 3-MMA fp32 emulation.
// logit_k = (2*<x,c_k> - |c_k|^2)/T  (x^2 cancels in softmax).
// R14: L1-wavefront surgery.
//  (1) Warp-cooperative reconstruction: 32 lanes gather one survivor codeword
//      row (512B coalesced LDG.128) instead of 8-rows-x-4-quarters scatter
//      (~8000 -> ~130 wavefronts/CTA). Coalesced output STG.128.
//  (2) B hi/lo fused into one uint4 image: 8 LDG.128/kt instead of 16 LDG.64.
// Survivor-list epilogue + direct-global B (R13) kept. 2 CTAs/SM.

#define KCW 256
#define DM  128
#define TILE_M 64
#define CAP 64            // survivor list capacity per row (expected ~3)

// ---- smem byte offsets ----
#define OFF_XH  0         // 17408: X stage hi (64 rows x 272B); lists after GEMM
#define OFF_XL  17408     // 17408: X stage lo
#define OFF_C2  34816     // 1024:  c2 * invT (256 f)
#define OFF_STM 35840     // 1024:  max partials [wc*64+row]
#define OFF_CNT 36864     // 256:   survivor counters (64 u32)
#define SMEM_TOTAL 37120
#define XSTRIDE 272       // bytes per staged X row (136 bf16)

// B fragment image, hi+lo fused per entry:
// uint4[(wc*8 + kt)*256... index = wc*2048 + kt*256 + j*32 + lane]
//   .x,.y = bh (k lo/hi pair), .z,.w = bl
__device__ __align__(16) uint4 g_bf[8][8192];
__device__ float g_c2[8 * KCW];

__device__ __forceinline__ void mma_bf16(float* d, const unsigned* a,
                                         unsigned bx, unsigned by) {
    asm volatile(
        "mma.sync.aligned.m16n8k16.row.col.f32.bf16.bf16.f32 "
        "{%0,%1,%2,%3}, {%4,%5,%6,%7}, {%8,%9}, {%0,%1,%2,%3};"
        : "+f"(d[0]), "+f"(d[1]), "+f"(d[2]), "+f"(d[3])
        : "r"(a[0]), "r"(a[1]), "r"(a[2]), "r"(a[3]), "r"(bx), "r"(by));
}

// ======================= prep kernel =======================
// Bakes codebook into fused hi/lo bf16 HMMA B-fragment image + c2.
// m16n8k16 col-major B frag: lane q=lane%4, g=lane/4; n = nt*8+g;
// reg.x = {k=kt*16+q*2, +1}, reg.y = {+8, +9}.   nt = wc*8 + j.
__global__ void prep_kernel(const float* __restrict__ cb) {
    int m = blockIdx.x, by = blockIdx.y, tid = threadIdx.x;
    if (by == 0) {
        const float* src = cb + ((size_t)m * KCW + tid) * DM;
        float c2 = 0.0f;
        for (int d4 = 0; d4 < DM; d4 += 4) {
            float4 v = *(const float4*)(src + d4);
            c2 = fmaf(v.x, v.x, c2); c2 = fmaf(v.y, v.y, c2);
            c2 = fmaf(v.z, v.z, c2); c2 = fmaf(v.w, v.w, c2);
        }
        g_c2[m * KCW + tid] = c2;
    }
#pragma unroll
    for (int i = 0; i < 8; ++i) {
        int e = by * 2048 + i * 256 + tid;
        int lane = e & 31, j = (e >> 5) & 7, kt = (e >> 8) & 7, wc = (e >> 11) & 3;
        int q = lane & 3, g = lane >> 2;
        int n = (wc * 8 + j) * 8 + g;
        int k0 = kt * 16 + q * 2;
        const float* src = cb + ((size_t)m * KCW + n) * DM;
        float f[4] = { src[k0], src[k0 + 1], src[k0 + 8], src[k0 + 9] };
        unsigned h[4], l[4];
#pragma unroll
        for (int u = 0; u < 4; ++u) {
            __nv_bfloat16 hb = __float2bfloat16_rn(f[u]);
            __nv_bfloat16 lb = __float2bfloat16_rn(f[u] - __bfloat162float(hb));
            h[u] = __bfloat16_as_ushort(hb);
            l[u] = __bfloat16_as_ushort(lb);
        }
        g_bf[m][e] = make_uint4(h[0] | (h[1] << 16), h[2] | (h[3] << 16),
                                l[0] | (l[1] << 16), l[2] | (l[3] << 16));
    }
}

// ======================= main kernel =======================
__global__ void __launch_bounds__(256, 2)
softpq_hmma_kernel(const float* __restrict__ x,
                   const float* __restrict__ cb,
                   const void* __restrict__ tptr,
                   float* __restrict__ out,
                   int N)
{
    extern __shared__ char smem[];
    const int tid  = threadIdx.x;
    const int wid  = tid >> 5;
    const int lane = tid & 31;
    const int q    = lane & 3;
    const int g    = lane >> 2;
    const int wr   = wid & 1;    // rows wr*32 .. wr*32+31
    const int wc   = wid >> 1;   // cols wc*64 .. wc*64+63
    const int m    = blockIdx.y;
    const int row0 = blockIdx.x * TILE_M;

    // temperature (robust to int32/float32 scalar encodings)
    float temp;
    {
        float tf = *(const float*)tptr;
        if (tf >= 1e-6f && tf <= 1e6f) temp = tf;
        else { int ti = *(const int*)tptr; temp = (ti != 0) ? (float)ti : 1.0f; }
    }
    const float inv_temp = 1.0f / temp;
    const float two_it = 2.0f * inv_temp;

    // survivor counters zeroed early (visible after the pre-GEMM syncthreads)
    if (tid < 64) ((unsigned*)(smem + OFF_CNT))[tid] = 0u;

    // --- X tile: coalesced load, hi/lo bf16 split, stage (272B row stride) ---
    {
#pragma unroll
        for (int it = 0; it < 8; ++it) {
            int f = tid + it * 256;           // float4 index
            int r = f >> 5, c4 = f & 31;      // whole warp on one row
            int gr = row0 + r;
            float4 v = make_float4(0.f, 0.f, 0.f, 0.f);
            if (gr < N)
                v = *(const float4*)(x + (size_t)gr * 1024 + m * DM + c4 * 4);
            float fv[4] = { v.x, v.y, v.z, v.w };
            unsigned h[4], l[4];
#pragma unroll
            for (int u = 0; u < 4; ++u) {
                __nv_bfloat16 hb = __float2bfloat16_rn(fv[u]);
                __nv_bfloat16 lb = __float2bfloat16_rn(fv[u] - __bfloat162float(hb));
                h[u] = __bfloat16_as_ushort(hb);
                l[u] = __bfloat16_as_ushort(lb);
            }
            *(uint2*)(smem + OFF_XH + r * XSTRIDE + c4 * 8) =
                make_uint2(h[0] | (h[1] << 16), h[2] | (h[3] << 16));
            *(uint2*)(smem + OFF_XL + r * XSTRIDE + c4 * 8) =
                make_uint2(l[0] | (l[1] << 16), l[2] | (l[3] << 16));
        }
    }

    // --- c2 * invT ---
    ((float*)(smem + OFF_C2))[tid] = g_c2[m * KCW + tid] * inv_temp;
    __syncthreads();           // X stage + counters visible

    // --- fused HMMA GEMM: B frags straight from global (L1-resident image) ---
    float acc[2][8][4];
#pragma unroll
    for (int mt = 0; mt < 2; ++mt)
#pragma unroll
        for (int j = 0; j < 8; ++j)
#pragma unroll
            for (int u = 0; u < 4; ++u) acc[mt][j][u] = 0.0f;

    const char* AbH = smem + OFF_XH + (wr * 32 + g) * XSTRIDE + q * 4;
    const char* AbL = smem + OFF_XL + (wr * 32 + g) * XSTRIDE + q * 4;
    const uint4* pB = g_bf[m] + wc * 2048 + lane;

#pragma unroll 1
    for (int kt = 0; kt < 8; ++kt) {
        // B frags for this kt: 8 independent LDG.128 (hi+lo fused)
        uint4 bb[8];
#pragma unroll
        for (int j = 0; j < 8; ++j) bb[j] = __ldg(pB + kt * 256 + j * 32);

        // A frags (hi + lo) from smem
        unsigned ah[2][4], al[2][4];
#pragma unroll
        for (int mt = 0; mt < 2; ++mt) {
            const char* hp = AbH + mt * (16 * XSTRIDE) + kt * 32;
            const char* lp = AbL + mt * (16 * XSTRIDE) + kt * 32;
            ah[mt][0] = *(const unsigned*)(hp);
            ah[mt][1] = *(const unsigned*)(hp + 8 * XSTRIDE);
            ah[mt][2] = *(const unsigned*)(hp + 16);
            ah[mt][3] = *(const unsigned*)(hp + 8 * XSTRIDE + 16);
            al[mt][0] = *(const unsigned*)(lp);
            al[mt][1] = *(const unsigned*)(lp + 8 * XSTRIDE);
            al[mt][2] = *(const unsigned*)(lp + 16);
            al[mt][3] = *(const unsigned*)(lp + 8 * XSTRIDE + 16);
        }

        // all 3 emulation passes fused: xh*bh, xl*bh, xh*bl
#pragma unroll
        for (int j = 0; j < 8; ++j) {
            mma_bf16(acc[0][j], ah[0], bb[j].x, bb[j].y);
            mma_bf16(acc[1][j], ah[1], bb[j].x, bb[j].y);
            mma_bf16(acc[0][j], al[0], bb[j].x, bb[j].y);
            mma_bf16(acc[1][j], al[1], bb[j].x, bb[j].y);
            mma_bf16(acc[0][j], ah[0], bb[j].z, bb[j].w);
            mma_bf16(acc[1][j], ah[1], bb[j].z, bb[j].w);
        }
    }

    // --- logits in registers + per-row quarter-MAX to smem ---
    {
        const float* c2s = (const float*)(smem + OFF_C2);
        float c2v[8][2];
#pragma unroll
        for (int j = 0; j < 8; ++j) {
            int col = wc * 64 + j * 8 + q * 2;
            c2v[j][0] = c2s[col];
            c2v[j][1] = c2s[col + 1];
        }
#pragma unroll
        for (int mt = 0; mt < 2; ++mt)
#pragma unroll
            for (int j = 0; j < 8; ++j) {
                acc[mt][j][0] = fmaf(acc[mt][j][0], two_it, -c2v[j][0]);
                acc[mt][j][1] = fmaf(acc[mt][j][1], two_it, -c2v[j][1]);
                acc[mt][j][2] = fmaf(acc[mt][j][2], two_it, -c2v[j][0]);
                acc[mt][j][3] = fmaf(acc[mt][j][3], two_it, -c2v[j][1]);
            }

        float* stm = (float*)(smem + OFF_STM);
#pragma unroll
        for (int mt = 0; mt < 2; ++mt)
#pragma unroll
            for (int rh = 0; rh < 2; ++rh) {
                float mv = -3.402823466e38f;
#pragma unroll
                for (int j = 0; j < 8; ++j) {
                    mv = fmaxf(mv, acc[mt][j][rh * 2 + 0]);
                    mv = fmaxf(mv, acc[mt][j][rh * 2 + 1]);
                }
                mv = fmaxf(mv, __shfl_xor_sync(0xffffffffu, mv, 1));
                mv = fmaxf(mv, __shfl_xor_sync(0xffffffffu, mv, 2));
                if (q == 0) stm[wc * 64 + (wr * 32 + mt * 16 + rh * 8 + g)] = mv;
            }
    }
    __syncthreads();   // stm complete; X-stage reads done -> region reusable as lists

    // --- survivor append: exp only within 16.6 of global row max ---
    // (dropped mass <= 1.6e-5 of S)
    {
        const float* stm = (const float*)(smem + OFF_STM);
        unsigned* cnt = (unsigned*)(smem + OFF_CNT);
        uint2* list = (uint2*)(smem + OFF_XH);
#pragma unroll
        for (int mt = 0; mt < 2; ++mt)
#pragma unroll
            for (int rh = 0; rh < 2; ++rh) {
                int row = wr * 32 + mt * 16 + rh * 8 + g;
                float M = fmaxf(fmaxf(stm[row], stm[64 + row]),
                                fmaxf(stm[128 + row], stm[192 + row]));
                float cut = M - 16.6f;
#pragma unroll
                for (int j = 0; j < 8; ++j) {
#pragma unroll
                    for (int u = 0; u < 2; ++u) {
                        float l = acc[mt][j][rh * 2 + u];
                        if (l > cut) {
                            unsigned idx = atomicAdd(&cnt[row], 1u);
                            if (idx < CAP) {
                                unsigned k = (unsigned)(wc * 64 + j * 8 + q * 2 + u);
                                list[row * CAP + idx] =
                                    make_uint2(k, __float_as_uint(__expf(l - M)));
                            }
                        }
                    }
                }
            }
    }
    __syncthreads();

    // --- warp-cooperative reconstruction: warp wid owns rows wid*8..wid*8+7 ---
    // For each row, all 32 lanes gather one survivor codeword row cooperatively
    // (one coalesced 512B LDG.128 per survivor), then one coalesced STG.128.
    {
        const unsigned* cnt = (const unsigned*)(smem + OFF_CNT);
        const uint2* list = (const uint2*)(smem + OFF_XH);
        const float* Cm = cb + (size_t)m * KCW * DM;

#pragma unroll 1
        for (int rr = 0; rr < 8; ++rr) {
            int row = wid * 8 + rr;
            int n = (int)cnt[row];
            if (n > CAP) n = CAP;
            const uint2* lrow = list + row * CAP;

            // S: lanes read list entries in parallel, warp-reduce
            float s = 0.0f;
            if (lane < n) s = __uint_as_float(lrow[lane].y);
            if (n > 32 && lane + 32 < n) s += __uint_as_float(lrow[lane + 32].y);
#pragma unroll
            for (int off = 16; off > 0; off >>= 1)
                s += __shfl_xor_sync(0xffffffffu, s, off);
            const float invS = 1.0f / s;

            float4 o = make_float4(0.f, 0.f, 0.f, 0.f);
#pragma unroll 2
            for (int i = 0; i < n; ++i) {
                uint2 ent = lrow[i];            // broadcast LDS
                float p = __uint_as_float(ent.y) * invS;
                float4 c = __ldg((const float4*)(Cm + (size_t)ent.x * DM) + lane);
                o.x = fmaf(p, c.x, o.x);
                o.y = fmaf(p, c.y, o.y);
                o.z = fmaf(p, c.z, o.z);
                o.w = fmaf(p, c.w, o.w);
            }

            int gr = row0 + row;
            if (gr < N)
                *((float4*)(out + (size_t)gr * 1024 + m * DM) + lane) = o;
        }
    }
}

extern "C" void kernel_launch(void* const* d_in, const int* in_sizes, int n_in,
                              void* d_out, int out_size)
{
    const float* x  = (const float*)d_in[0];
    const float* cb = (const float*)d_in[1];
    const void*  t  = d_in[2];
    float* out = (float*)d_out;

    int N = in_sizes[0] / 1024;   // D = M*D_M = 1024

    prep_kernel<<<dim3(8, 4), 256>>>(cb);

    cudaFuncSetAttribute(softpq_hmma_kernel,
                         cudaFuncAttributeMaxDynamicSharedMemorySize, SMEM_TOTAL);
    dim3 grid((N + TILE_M - 1) / TILE_M, 8);
    softpq_hmma_kernel<<<grid, 256, SMEM_TOTAL>>>(x, cb, t, out, N);
}

// round 15
// speedup vs baseline: 2.4242x; 1.0363x over previous
#include <cuda_runtime.h>
#include <cuda_bf16.h>

// Soft-PQ via warp-level HMMA (mma.sync m16n8k16 bf16), hi/lo 3-MMA fp32 emulation.
// logit_k = (2*<x,c_k> - |c_k|^2)/T  (x^2 cancels in softmax).
// R15: SOFTWARE-PIPELINED B — ping-pong 4-frag buffers at j-half granularity
// (b1 LDGs fly under b0's 24 MMAs and vice versa); first chunk prefetched
// BEFORE X staging so its L2 miss hides under the load phase.
// Warp-coop recon + survivor lists + fused hi/lo B image (R14) kept. 2 CTAs/SM.

#define KCW 256
#define DM  128
#define TILE_M 64
#define CAP 64            // survivor list capacity per row (expected ~3)

// ---- smem byte offsets ----
#define OFF_XH  0         // 17408: X stage hi (64 rows x 272B); lists after GEMM
#define OFF_XL  17408     // 17408: X stage lo
#define OFF_C2  34816     // 1024:  c2 * invT (256 f)
#define OFF_STM 35840     // 1024:  max partials [wc*64+row]
#define OFF_CNT 36864     // 256:   survivor counters (64 u32)
#define SMEM_TOTAL 37120
#define XSTRIDE 272       // bytes per staged X row (136 bf16)

// B fragment image, hi+lo fused per entry:
// index = wc*2048 + kt*256 + j*32 + lane   (uint4: .x,.y = bh, .z,.w = bl)
__device__ __align__(16) uint4 g_bf[8][8192];
__device__ float g_c2[8 * KCW];

__device__ __forceinline__ void mma_bf16(float* d, const unsigned* a,
                                         unsigned bx, unsigned by) {
    asm volatile(
        "mma.sync.aligned.m16n8k16.row.col.f32.bf16.bf16.f32 "
        "{%0,%1,%2,%3}, {%4,%5,%6,%7}, {%8,%9}, {%0,%1,%2,%3};"
        : "+f"(d[0]), "+f"(d[1]), "+f"(d[2]), "+f"(d[3])
        : "r"(a[0]), "r"(a[1]), "r"(a[2]), "r"(a[3]), "r"(bx), "r"(by));
}

// ======================= prep kernel =======================
// Bakes codebook into fused hi/lo bf16 HMMA B-fragment image + c2.
// m16n8k16 col-major B frag: lane q=lane%4, g=lane/4; n = nt*8+g;
// reg.x = {k=kt*16+q*2, +1}, reg.y = {+8, +9}.   nt = wc*8 + j.
__global__ void prep_kernel(const float* __restrict__ cb) {
    int m = blockIdx.x, by = blockIdx.y, tid = threadIdx.x;
    if (by == 0) {
        const float* src = cb + ((size_t)m * KCW + tid) * DM;
        float c2 = 0.0f;
        for (int d4 = 0; d4 < DM; d4 += 4) {
            float4 v = *(const float4*)(src + d4);
            c2 = fmaf(v.x, v.x, c2); c2 = fmaf(v.y, v.y, c2);
            c2 = fmaf(v.z, v.z, c2); c2 = fmaf(v.w, v.w, c2);
        }
        g_c2[m * KCW + tid] = c2;
    }
#pragma unroll
    for (int i = 0; i < 8; ++i) {
        int e = by * 2048 + i * 256 + tid;
        int lane = e & 31, j = (e >> 5) & 7, kt = (e >> 8) & 7, wc = (e >> 11) & 3;
        int q = lane & 3, g = lane >> 2;
        int n = (wc * 8 + j) * 8 + g;
        int k0 = kt * 16 + q * 2;
        const float* src = cb + ((size_t)m * KCW + n) * DM;
        float f[4] = { src[k0], src[k0 + 1], src[k0 + 8], src[k0 + 9] };
        unsigned h[4], l[4];
#pragma unroll
        for (int u = 0; u < 4; ++u) {
            __nv_bfloat16 hb = __float2bfloat16_rn(f[u]);
            __nv_bfloat16 lb = __float2bfloat16_rn(f[u] - __bfloat162float(hb));
            h[u] = __bfloat16_as_ushort(hb);
            l[u] = __bfloat16_as_ushort(lb);
        }
        g_bf[m][e] = make_uint4(h[0] | (h[1] << 16), h[2] | (h[3] << 16),
                                l[0] | (l[1] << 16), l[2] | (l[3] << 16));
    }
}

// ======================= main kernel =======================
__global__ void __launch_bounds__(256, 2)
softpq_hmma_kernel(const float* __restrict__ x,
                   const float* __restrict__ cb,
                   const void* __restrict__ tptr,
                   float* __restrict__ out,
                   int N)
{
    extern __shared__ char smem[];
    const int tid  = threadIdx.x;
    const int wid  = tid >> 5;
    const int lane = tid & 31;
    const int q    = lane & 3;
    const int g    = lane >> 2;
    const int wr   = wid & 1;    // rows wr*32 .. wr*32+31
    const int wc   = wid >> 1;   // cols wc*64 .. wc*64+63
    const int m    = blockIdx.y;
    const int row0 = blockIdx.x * TILE_M;

    // temperature (robust to int32/float32 scalar encodings)
    float temp;
    {
        float tf = *(const float*)tptr;
        if (tf >= 1e-6f && tf <= 1e6f) temp = tf;
        else { int ti = *(const int*)tptr; temp = (ti != 0) ? (float)ti : 1.0f; }
    }
    const float inv_temp = 1.0f / temp;
    const float two_it = 2.0f * inv_temp;

    const uint4* pB = g_bf[m] + wc * 2048 + lane;

    // --- pipeline prologue: first B half-chunk in flight BEFORE X staging,
    //     so its L2 miss hides under the X load/convert phase ---
    uint4 b0[4], b1[4];
#pragma unroll
    for (int j = 0; j < 4; ++j) b0[j] = __ldg(pB + j * 32);

    // survivor counters zeroed early (visible after the pre-GEMM syncthreads)
    if (tid < 64) ((unsigned*)(smem + OFF_CNT))[tid] = 0u;

    // --- X tile: coalesced load, hi/lo bf16 split, stage (272B row stride) ---
    {
#pragma unroll
        for (int it = 0; it < 8; ++it) {
            int f = tid + it * 256;           // float4 index
            int r = f >> 5, c4 = f & 31;      // whole warp on one row
            int gr = row0 + r;
            float4 v = make_float4(0.f, 0.f, 0.f, 0.f);
            if (gr < N)
                v = *(const float4*)(x + (size_t)gr * 1024 + m * DM + c4 * 4);
            float fv[4] = { v.x, v.y, v.z, v.w };
            unsigned h[4], l[4];
#pragma unroll
            for (int u = 0; u < 4; ++u) {
                __nv_bfloat16 hb = __float2bfloat16_rn(fv[u]);
                __nv_bfloat16 lb = __float2bfloat16_rn(fv[u] - __bfloat162float(hb));
                h[u] = __bfloat16_as_ushort(hb);
                l[u] = __bfloat16_as_ushort(lb);
            }
            *(uint2*)(smem + OFF_XH + r * XSTRIDE + c4 * 8) =
                make_uint2(h[0] | (h[1] << 16), h[2] | (h[3] << 16));
            *(uint2*)(smem + OFF_XL + r * XSTRIDE + c4 * 8) =
                make_uint2(l[0] | (l[1] << 16), l[2] | (l[3] << 16));
        }
    }

    // --- c2 * invT ---
    ((float*)(smem + OFF_C2))[tid] = g_c2[m * KCW + tid] * inv_temp;
    __syncthreads();           // X stage + counters visible

    // --- fused, software-pipelined HMMA GEMM ---
    float acc[2][8][4];
#pragma unroll
    for (int mt = 0; mt < 2; ++mt)
#pragma unroll
        for (int j = 0; j < 8; ++j)
#pragma unroll
            for (int u = 0; u < 4; ++u) acc[mt][j][u] = 0.0f;

    const char* AbH = smem + OFF_XH + (wr * 32 + g) * XSTRIDE + q * 4;
    const char* AbL = smem + OFF_XL + (wr * 32 + g) * XSTRIDE + q * 4;

#pragma unroll 1
    for (int kt = 0; kt < 8; ++kt) {
        // issue b1 <- (kt, j=4..7) before touching b0
#pragma unroll
        for (int j = 0; j < 4; ++j) b1[j] = __ldg(pB + kt * 256 + 128 + j * 32);

        // A frags (hi + lo) from smem, once per kt
        unsigned ah[2][4], al[2][4];
#pragma unroll
        for (int mt = 0; mt < 2; ++mt) {
            const char* hp = AbH + mt * (16 * XSTRIDE) + kt * 32;
            const char* lp = AbL + mt * (16 * XSTRIDE) + kt * 32;
            ah[mt][0] = *(const unsigned*)(hp);
            ah[mt][1] = *(const unsigned*)(hp + 8 * XSTRIDE);
            ah[mt][2] = *(const unsigned*)(hp + 16);
            ah[mt][3] = *(const unsigned*)(hp + 8 * XSTRIDE + 16);
            al[mt][0] = *(const unsigned*)(lp);
            al[mt][1] = *(const unsigned*)(lp + 8 * XSTRIDE);
            al[mt][2] = *(const unsigned*)(lp + 16);
            al[mt][3] = *(const unsigned*)(lp + 8 * XSTRIDE + 16);
        }

        // 24 MMAs on b0 (j = 0..3) while b1 is in flight
#pragma unroll
        for (int j = 0; j < 4; ++j) {
            mma_bf16(acc[0][j], ah[0], b0[j].x, b0[j].y);
            mma_bf16(acc[1][j], ah[1], b0[j].x, b0[j].y);
            mma_bf16(acc[0][j], al[0], b0[j].x, b0[j].y);
            mma_bf16(acc[1][j], al[1], b0[j].x, b0[j].y);
            mma_bf16(acc[0][j], ah[0], b0[j].z, b0[j].w);
            mma_bf16(acc[1][j], ah[1], b0[j].z, b0[j].w);
        }

        // issue b0 <- (kt+1, j=0..3) while b1's MMAs run (kt=7: dummy reload)
        int ktn = (kt < 7) ? kt + 1 : 7;
#pragma unroll
        for (int j = 0; j < 4; ++j) b0[j] = __ldg(pB + ktn * 256 + j * 32);

        // 24 MMAs on b1 (j = 4..7)
#pragma unroll
        for (int j = 0; j < 4; ++j) {
            mma_bf16(acc[0][4 + j], ah[0], b1[j].x, b1[j].y);
            mma_bf16(acc[1][4 + j], ah[1], b1[j].x, b1[j].y);
            mma_bf16(acc[0][4 + j], al[0], b1[j].x, b1[j].y);
            mma_bf16(acc[1][4 + j], al[1], b1[j].x, b1[j].y);
            mma_bf16(acc[0][4 + j], ah[0], b1[j].z, b1[j].w);
            mma_bf16(acc[1][4 + j], ah[1], b1[j].z, b1[j].w);
        }
    }

    // --- logits in registers + per-row quarter-MAX to smem ---
    {
        const float* c2s = (const float*)(smem + OFF_C2);
        float c2v[8][2];
#pragma unroll
        for (int j = 0; j < 8; ++j) {
            int col = wc * 64 + j * 8 + q * 2;
            c2v[j][0] = c2s[col];
            c2v[j][1] = c2s[col + 1];
        }
#pragma unroll
        for (int mt = 0; mt < 2; ++mt)
#pragma unroll
            for (int j = 0; j < 8; ++j) {
                acc[mt][j][0] = fmaf(acc[mt][j][0], two_it, -c2v[j][0]);
                acc[mt][j][1] = fmaf(acc[mt][j][1], two_it, -c2v[j][1]);
                acc[mt][j][2] = fmaf(acc[mt][j][2], two_it, -c2v[j][0]);
                acc[mt][j][3] = fmaf(acc[mt][j][3], two_it, -c2v[j][1]);
            }

        float* stm = (float*)(smem + OFF_STM);
#pragma unroll
        for (int mt = 0; mt < 2; ++mt)
#pragma unroll
            for (int rh = 0; rh < 2; ++rh) {
                float mv = -3.402823466e38f;
#pragma unroll
                for (int j = 0; j < 8; ++j) {
                    mv = fmaxf(mv, acc[mt][j][rh * 2 + 0]);
                    mv = fmaxf(mv, acc[mt][j][rh * 2 + 1]);
                }
                mv = fmaxf(mv, __shfl_xor_sync(0xffffffffu, mv, 1));
                mv = fmaxf(mv, __shfl_xor_sync(0xffffffffu, mv, 2));
                if (q == 0) stm[wc * 64 + (wr * 32 + mt * 16 + rh * 8 + g)] = mv;
            }
    }
    __syncthreads();   // stm complete; X-stage reads done -> region reusable as lists

    // --- survivor append: exp only within 16.6 of global row max ---
    // (dropped mass <= 1.6e-5 of S)
    {
        const float* stm = (const float*)(smem + OFF_STM);
        unsigned* cnt = (unsigned*)(smem + OFF_CNT);
        uint2* list = (uint2*)(smem + OFF_XH);
#pragma unroll
        for (int mt = 0; mt < 2; ++mt)
#pragma unroll
            for (int rh = 0; rh < 2; ++rh) {
                int row = wr * 32 + mt * 16 + rh * 8 + g;
                float M = fmaxf(fmaxf(stm[row], stm[64 + row]),
                                fmaxf(stm[128 + row], stm[192 + row]));
                float cut = M - 16.6f;
#pragma unroll
                for (int j = 0; j < 8; ++j) {
#pragma unroll
                    for (int u = 0; u < 2; ++u) {
                        float l = acc[mt][j][rh * 2 + u];
                        if (l > cut) {
                            unsigned idx = atomicAdd(&cnt[row], 1u);
                            if (idx < CAP) {
                                unsigned k = (unsigned)(wc * 64 + j * 8 + q * 2 + u);
                                list[row * CAP + idx] =
                                    make_uint2(k, __float_as_uint(__expf(l - M)));
                            }
                        }
                    }
                }
            }
    }
    __syncthreads();

    // --- warp-cooperative reconstruction: warp wid owns rows wid*8..wid*8+7 ---
    {
        const unsigned* cnt = (const unsigned*)(smem + OFF_CNT);
        const uint2* list = (const uint2*)(smem + OFF_XH);
        const float* Cm = cb + (size_t)m * KCW * DM;

#pragma unroll 1
        for (int rr = 0; rr < 8; ++rr) {
            int row = wid * 8 + rr;
            int n = (int)cnt[row];
            if (n > CAP) n = CAP;
            const uint2* lrow = list + row * CAP;

            // S: lanes read list entries in parallel, warp-reduce
            float s = 0.0f;
            if (lane < n) s = __uint_as_float(lrow[lane].y);
            if (n > 32 && lane + 32 < n) s += __uint_as_float(lrow[lane + 32].y);
#pragma unroll
            for (int off = 16; off > 0; off >>= 1)
                s += __shfl_xor_sync(0xffffffffu, s, off);
            const float invS = 1.0f / s;

            float4 o = make_float4(0.f, 0.f, 0.f, 0.f);
#pragma unroll 2
            for (int i = 0; i < n; ++i) {
                uint2 ent = lrow[i];            // broadcast LDS
                float p = __uint_as_float(ent.y) * invS;
                float4 c = __ldg((const float4*)(Cm + (size_t)ent.x * DM) + lane);
                o.x = fmaf(p, c.x, o.x);
                o.y = fmaf(p, c.y, o.y);
                o.z = fmaf(p, c.z, o.z);
                o.w = fmaf(p, c.w, o.w);
            }

            int gr = row0 + row;
            if (gr < N)
                *((float4*)(out + (size_t)gr * 1024 + m * DM) + lane) = o;
        }
    }
}

extern "C" void kernel_launch(void* const* d_in, const int* in_sizes, int n_in,
                              void* d_out, int out_size)
{
    const float* x  = (const float*)d_in[0];
    const float* cb = (const float*)d_in[1];
    const void*  t  = d_in[2];
    float* out = (float*)d_out;

    int N = in_sizes[0] / 1024;   // D = M*D_M = 1024

    prep_kernel<<<dim3(8, 4), 256>>>(cb);

    cudaFuncSetAttribute(softpq_hmma_kernel,
                         cudaFuncAttributeMaxDynamicSharedMemorySize, SMEM_TOTAL);
    dim3 grid((N + TILE_M - 1) / TILE_M, 8);
    softpq_hmma_kernel<<<grid, 256, SMEM_TOTAL>>>(x, cb, t, out, N);
}